// round 9
// baseline (speedup 1.0000x reference)
#include <cuda_runtime.h>

#define C_DIM 4096
#define N_F 8
#define NPAIR 36            // 8*9/2, i<=j
#define EPS_F 1e-8f
#define NTILE 32            // 4096 / 128
#define NCROSSB (528 * 2)   // 1056: triangle tiles x 2 v-halves
#define NROWB 256           // 16-u x 8-factor rowsum blocks
#define NBLOCKS (NCROSSB + NROWB)   // 1312
#define NSTOT (2 * NPAIR + N_F)     // [0,36): rowdots  [36,72): cross  [72,80): fsum

// Device globals (statics start zero; winner block re-zeroes for graph replay).
__device__ float g_stot[NSTOT];
__device__ unsigned int g_ctr = 0;

// Single fused kernel.
//  bid % 5 == 4 && bid < 1280 -> rowsum block rb=(bid-4)/5   (256 blocks)
//  otherwise                  -> cross block (1056 blocks)
// Last block to finish (ticket) does the tiny 8x8 final math.
__global__ __launch_bounds__(128, 8) void main_kernel(const float* __restrict__ x,
                                                      float* __restrict__ out) {
    __shared__ union {
        struct {
            float v[64][N_F];        // cross: v-half values [vi][f]
            float red[4][NPAIR];     // cross: per-warp partials
        } c;
        float h[16][N_F + 1];        // rowsum: complete rowsums for the u-tile
        struct {
            float sdc[NPAIR];        // epilogue: dcov
            float sm[N_F];
        } e;
    } sh;
    __shared__ unsigned sh_rank;

    const int tid = threadIdx.x;
    const int bid = blockIdx.x;
    const int lane = tid & 31;
    const int warp = tid >> 5;

    const bool is_row = ((bid % 5) == 4) && (bid < 1280);

    if (!is_row) {
        // ---------------- cross path (R7-proven, unchanged) ----------------
        int nr = (bid + 1) / 5; if (nr > NROWB) nr = NROWB;
        const int ci = bid - nr;            // [0, 1056)
        const int tile = ci >> 1;
        const int vh = ci & 1;
        int rem = tile, ti = 0;
        while (rem >= NTILE - ti) { rem -= NTILE - ti; ti++; }
        const int tj = ti + rem;
        const int vb = tj * 128 + vh * 64;

        for (int i = tid; i < 64 * N_F; i += 128) {
            int f = i >> 6, vi = i & 63;
            sh.c.v[vi][f] = x[f * C_DIM + vb + vi];
        }

        const int u = ti * 128 + tid;
        float xu[N_F];
#pragma unroll
        for (int f = 0; f < N_F; f++) xu[f] = x[f * C_DIM + u];

        __syncthreads();

        float acc[NPAIR];
#pragma unroll
        for (int k = 0; k < NPAIR; k++) acc[k] = 0.0f;

#pragma unroll 2
        for (int vi = 0; vi < 64; vi++) {
            float4 p0 = *reinterpret_cast<const float4*>(&sh.c.v[vi][0]);
            float4 p1 = *reinterpret_cast<const float4*>(&sh.c.v[vi][4]);
            float xv[N_F] = {p0.x, p0.y, p0.z, p0.w, p1.x, p1.y, p1.z, p1.w};

            float a[N_F];
#pragma unroll
            for (int f = 0; f < N_F; f++) a[f] = fabsf(xu[f] - xv[f]);

            int k = 0;
#pragma unroll
            for (int i = 0; i < N_F; i++)
#pragma unroll
                for (int j = i; j < N_F; j++) {
                    acc[k] = fmaf(a[i], a[j], acc[k]);
                    k++;
                }
        }

        // Diagonal tiles internally symmetric: weight 0.5 (self terms are 0).
        const float w = (ti == tj) ? 0.5f : 1.0f;
#pragma unroll
        for (int k = 0; k < NPAIR; k++) {
            float v = acc[k];
            for (int o = 16; o; o >>= 1) v += __shfl_down_sync(0xffffffffu, v, o);
            if (lane == 0) sh.c.red[warp][k] = v;
        }
        __syncthreads();
        if (tid < NPAIR) {
            float v = (sh.c.red[0][tid] + sh.c.red[1][tid]
                     + sh.c.red[2][tid] + sh.c.red[3][tid]) * w;
            atomicAdd(&g_stot[NPAIR + tid], v);
        }
    } else {
        // -------- rowsum path: thread = (u, f), stream row from global --------
        // Warp has only 2 distinct f's -> every LDG is a 2-address broadcast,
        // row (16 KB) L1-resident. No smem staging, no mid-loop barriers.
        const int rb = (bid - 4) / 5;       // [0, 256)
        const int uloc = tid & 15;
        const int f = tid >> 4;             // 0..7
        const int u = rb * 16 + uloc;
        const float xu = x[f * C_DIM + u];
        const float4* xf4 = reinterpret_cast<const float4*>(x + f * C_DIM);

        float r0 = 0.f, r1 = 0.f, r2 = 0.f, r3 = 0.f;
#pragma unroll 8
        for (int p = 0; p < C_DIM / 4; p++) {
            float4 q = xf4[p];
            r0 += fabsf(xu - q.x);
            r1 += fabsf(xu - q.y);
            r2 += fabsf(xu - q.z);
            r3 += fabsf(xu - q.w);
        }
        sh.h[uloc][f] = (r0 + r1) + (r2 + r3);
        __syncthreads();

        // Local rowdot partials over the 16 u's + factor sums -> one atomic each.
        if (tid < NPAIR) {
            int kk = tid, i = 0;
            while (kk >= N_F - i) { kk -= N_F - i; i++; }
            int j = i + kk;
            float s = 0.0f;
#pragma unroll
            for (int uu = 0; uu < 16; uu++)
                s = fmaf(sh.h[uu][i], sh.h[uu][j], s);
            atomicAdd(&g_stot[tid], s);
        } else if (tid >= 64 && tid < 64 + N_F) {
            int ff = tid - 64;
            float s = 0.0f;
#pragma unroll
            for (int uu = 0; uu < 16; uu++) s += sh.h[uu][ff];
            atomicAdd(&g_stot[2 * NPAIR + ff], s);
        }
    }

    // ---------------- ticket: last block does the final 8x8 math ----------------
    __threadfence();
    if (tid == 0) sh_rank = atomicAdd(&g_ctr, 1);
    __syncthreads();
    if (sh_rank != NBLOCKS - 1) return;

    const float fC = (float)C_DIM;
    const float invC2 = 1.0f / (fC * fC);

    __syncthreads();   // smem union handoff
    if (tid < N_F) sh.e.sm[tid] = __ldcg(&g_stot[2 * NPAIR + tid]) * invC2;
    __syncthreads();

    if (tid < NPAIR) {
        int kk = tid, i = 0;
        while (kk >= N_F - i) { kk -= N_F - i; i++; }
        int j = i + kk;
        // S = 2*cross_tri/C^2 - 2*rowdot/C^3 + m_i*m_j
        float s = 2.0f * __ldcg(&g_stot[NPAIR + tid]) * invC2
                - 2.0f * __ldcg(&g_stot[tid]) * invC2 / fC
                + sh.e.sm[i] * sh.e.sm[j];
        sh.e.sdc[tid] = sqrtf(fmaxf(s, 0.0f) + EPS_F);
    }
    __syncthreads();

    if (tid == 0) {
        float cor = 0.0f;
        for (int i = 0; i < N_F; i++) {
            int di = i * N_F - (i * (i - 1)) / 2;        // k(i,i)
            for (int j = i + 1; j < N_F; j++) {
                int dj = j * N_F - (j * (j - 1)) / 2;    // k(j,j)
                int kij = di + (j - i);                   // k(i,j)
                cor += sh.e.sdc[kij] / sqrtf(sh.e.sdc[di] * sh.e.sdc[dj] + EPS_F);
            }
        }
        out[0] = cor;
    }
    __syncthreads();

    // Reset scratch for next graph replay (all reads done above).
    if (tid < NSTOT) g_stot[tid] = 0.0f;
    if (tid == 0) g_ctr = 0;
}

extern "C" void kernel_launch(void* const* d_in, const int* in_sizes, int n_in,
                              void* d_out, int out_size) {
    const float* x = (const float*)d_in[0];
    float* out = (float*)d_out;
    main_kernel<<<NBLOCKS, 128>>>(x, out);
}

// round 10
// speedup vs baseline: 1.3081x; 1.3081x over previous
#include <cuda_runtime.h>

#define C_DIM 4096
#define N_F 8
#define NPAIR 36            // 8*9/2, i<=j
#define EPS_F 1e-8f
#define NTILE 32            // 4096 / 128
#define NROWB 256           // (u-tile, factor) full-row rowsum blocks
#define NCROSSB (528 * 2)   // 1056: triangle tiles x 2 v-halves
#define NBLOCKS (NROWB + NCROSSB)   // 1312
#define NSTOT (2 * NPAIR + N_F)     // [0,36): rowdots  [36,72): cross  [72,80): fsum

// Device globals (statics start zero; tickets/accumulators reset for graph replay).
__device__ float g_rowsum[N_F * C_DIM];
__device__ float g_stot[NSTOT];
__device__ unsigned int g_tile_ctr[NTILE];
__device__ unsigned int g_ctr = 0;

__global__ __launch_bounds__(128, 8) void main_kernel(const float* __restrict__ x,
                                                      float* __restrict__ out) {
    __shared__ union {
        float row[C_DIM];            // rowsum: negated full row, 16 KB
        struct {
            float v[64][N_F];        // cross: v-half values [vi][f]
            float red[4][NPAIR];     // cross: per-warp partials
        } c;
        float tred[4][NPAIR + N_F];  // tile-reduce partials
        struct {
            float sdc[NPAIR];        // final math
            float sm[N_F];
        } e;
    } sh;
    __shared__ unsigned sh_rank;

    const int tid = threadIdx.x;
    const int bid = blockIdx.x;
    const int lane = tid & 31;
    const int warp = tid >> 5;

    if (bid < NROWB) {
        // ---------- rowsum path (R7-proven structure, full row) ----------
        const int ut = bid >> 3;           // u-tile 0..31
        const int f = bid & 7;             // factor
        const float* xf = x + f * C_DIM;

        for (int i = tid; i < C_DIM; i += 128) sh.row[i] = -xf[i];

        const int u = ut * 128 + tid;
        const float xu = xf[u];
        __syncthreads();

        float r0 = 0.f, r1 = 0.f, r2 = 0.f, r3 = 0.f;
        const float4* row4 = (const float4*)sh.row;
#pragma unroll 8
        for (int p = 0; p < C_DIM / 4; p++) {
            float4 q = row4[p];
            r0 += fabsf(xu + q.x);
            r1 += fabsf(xu + q.y);
            r2 += fabsf(xu + q.z);
            r3 += fabsf(xu + q.w);
        }
        g_rowsum[f * C_DIM + u] = (r0 + r1) + (r2 + r3);

        // ---- per-u-tile ticket: 8th block of this tile reduces the rowdots ----
        __threadfence();
        if (tid == 0) sh_rank = atomicAdd(&g_tile_ctr[ut], 1);
        __syncthreads();
        if (sh_rank == N_F - 1) {
            float r[N_F];
#pragma unroll
            for (int ff = 0; ff < N_F; ff++)
                r[ff] = __ldcg(&g_rowsum[ff * C_DIM + u]);

            // Immediate shuffle-reduce per pair: one temp live at a time.
            __syncthreads();   // smem union handoff (row -> tred)
            int k = 0;
#pragma unroll
            for (int i = 0; i < N_F; i++) {
#pragma unroll
                for (int j = i; j < N_F; j++) {
                    float v = r[i] * r[j];
                    for (int o = 16; o; o >>= 1) v += __shfl_down_sync(0xffffffffu, v, o);
                    if (lane == 0) sh.tred[warp][k] = v;
                    k++;
                }
            }
#pragma unroll
            for (int ff = 0; ff < N_F; ff++) {
                float v = r[ff];
                for (int o = 16; o; o >>= 1) v += __shfl_down_sync(0xffffffffu, v, o);
                if (lane == 0) sh.tred[warp][NPAIR + ff] = v;
            }
            __syncthreads();
            if (tid < NPAIR + N_F) {
                float v = sh.tred[0][tid] + sh.tred[1][tid]
                        + sh.tred[2][tid] + sh.tred[3][tid];
                int dst = (tid < NPAIR) ? tid : (2 * NPAIR + (tid - NPAIR));
                atomicAdd(&g_stot[dst], v);
            }
            if (tid == 0) g_tile_ctr[ut] = 0;   // reset for next replay
        }
    } else {
        // ---------------- cross path (R7-proven, unchanged) ----------------
        const int ci = bid - NROWB;         // [0, 1056)
        const int tile = ci >> 1;
        const int vh = ci & 1;
        int rem = tile, ti = 0;
        while (rem >= NTILE - ti) { rem -= NTILE - ti; ti++; }
        const int tj = ti + rem;
        const int vb = tj * 128 + vh * 64;

        for (int i = tid; i < 64 * N_F; i += 128) {
            int f = i >> 6, vi = i & 63;
            sh.c.v[vi][f] = x[f * C_DIM + vb + vi];
        }

        const int u = ti * 128 + tid;
        float xu[N_F];
#pragma unroll
        for (int f = 0; f < N_F; f++) xu[f] = x[f * C_DIM + u];

        __syncthreads();

        float acc[NPAIR];
#pragma unroll
        for (int k = 0; k < NPAIR; k++) acc[k] = 0.0f;

#pragma unroll 2
        for (int vi = 0; vi < 64; vi++) {
            float4 p0 = *reinterpret_cast<const float4*>(&sh.c.v[vi][0]);
            float4 p1 = *reinterpret_cast<const float4*>(&sh.c.v[vi][4]);
            float xv[N_F] = {p0.x, p0.y, p0.z, p0.w, p1.x, p1.y, p1.z, p1.w};

            float a[N_F];
#pragma unroll
            for (int f = 0; f < N_F; f++) a[f] = fabsf(xu[f] - xv[f]);

            int k = 0;
#pragma unroll
            for (int i = 0; i < N_F; i++)
#pragma unroll
                for (int j = i; j < N_F; j++) {
                    acc[k] = fmaf(a[i], a[j], acc[k]);
                    k++;
                }
        }

        // Diagonal tiles internally symmetric: weight 0.5 (self terms are 0).
        const float w = (ti == tj) ? 0.5f : 1.0f;
#pragma unroll
        for (int k = 0; k < NPAIR; k++) {
            float v = acc[k];
            for (int o = 16; o; o >>= 1) v += __shfl_down_sync(0xffffffffu, v, o);
            if (lane == 0) sh.c.red[warp][k] = v;
        }
        __syncthreads();
        if (tid < NPAIR) {
            float v = (sh.c.red[0][tid] + sh.c.red[1][tid]
                     + sh.c.red[2][tid] + sh.c.red[3][tid]) * w;
            atomicAdd(&g_stot[NPAIR + tid], v);
        }
    }

    // ---------------- global ticket: last block does the 8x8 math ----------------
    __threadfence();
    if (tid == 0) sh_rank = atomicAdd(&g_ctr, 1);
    __syncthreads();
    if (sh_rank != NBLOCKS - 1) return;

    const float fC = (float)C_DIM;
    const float invC2 = 1.0f / (fC * fC);

    __syncthreads();   // smem union handoff
    if (tid < N_F) sh.e.sm[tid] = __ldcg(&g_stot[2 * NPAIR + tid]) * invC2;
    __syncthreads();

    if (tid < NPAIR) {
        int kk = tid, i = 0;
        while (kk >= N_F - i) { kk -= N_F - i; i++; }
        int j = i + kk;
        // S = 2*cross_tri/C^2 - 2*rowdot/C^3 + m_i*m_j
        float s = 2.0f * __ldcg(&g_stot[NPAIR + tid]) * invC2
                - 2.0f * __ldcg(&g_stot[tid]) * invC2 / fC
                + sh.e.sm[i] * sh.e.sm[j];
        sh.e.sdc[tid] = sqrtf(fmaxf(s, 0.0f) + EPS_F);
    }
    __syncthreads();

    if (tid == 0) {
        float cor = 0.0f;
        for (int i = 0; i < N_F; i++) {
            int di = i * N_F - (i * (i - 1)) / 2;        // k(i,i)
            for (int j = i + 1; j < N_F; j++) {
                int dj = j * N_F - (j * (j - 1)) / 2;    // k(j,j)
                int kij = di + (j - i);                   // k(i,j)
                cor += sh.e.sdc[kij] / sqrtf(sh.e.sdc[di] * sh.e.sdc[dj] + EPS_F);
            }
        }
        out[0] = cor;
    }
    __syncthreads();

    // Reset accumulators/ticket for next graph replay (all reads done above).
    if (tid < NSTOT) g_stot[tid] = 0.0f;
    if (tid == 0) g_ctr = 0;
}

extern "C" void kernel_launch(void* const* d_in, const int* in_sizes, int n_in,
                              void* d_out, int out_size) {
    const float* x = (const float*)d_in[0];
    float* out = (float*)d_out;
    main_kernel<<<NBLOCKS, 128>>>(x, out);
}

// round 11
// speedup vs baseline: 1.3091x; 1.0008x over previous
#include <cuda_runtime.h>

#define C_DIM 4096
#define N_F 8
#define NPAIR 36            // 8*9/2, i<=j
#define EPS_F 1e-8f
#define NTILE 32            // 4096 / 128
#define NCROSSB (528 * 2)   // 1056: triangle tiles x 2 v-halves
#define NROWB 512           // (u-tile, factor, v-half) rowsum blocks
#define NBLOCKS (NCROSSB + NROWB)   // 1568
#define NSTOT (2 * NPAIR + N_F)     // [0,36): rowdots  [36,72): cross  [72,80): fsum

// Device globals (statics start zero; tickets/accumulators reset for graph replay).
__device__ float g_rowsum2[2][N_F * C_DIM];  // halved rowsums
__device__ float g_stot[NSTOT];
__device__ unsigned int g_tile_ctr[NTILE];
__device__ unsigned int g_ctr = 0;

__global__ __launch_bounds__(128, 8) void main_kernel(const float* __restrict__ x,
                                                      float* __restrict__ out) {
    __shared__ union {
        float row[2048];             // rowsum: negated v-half, 8 KB
        struct {
            float v[64][N_F];        // cross: v-half values [vi][f]
            float red[4][NPAIR];     // cross: per-warp partials
        } c;
        float tred[4][NPAIR + N_F];  // tile-reduce partials
        struct {
            float sdc[NPAIR];        // final math
            float sm[N_F];
        } e;
    } sh;
    __shared__ unsigned sh_rank;

    const int tid = threadIdx.x;
    const int bid = blockIdx.x;
    const int lane = tid & 31;
    const int warp = tid >> 5;

    if (bid < NCROSSB) {
        // ---------------- cross path (R7-proven, unchanged) ----------------
        const int ci = bid;
        const int tile = ci >> 1;
        const int vh = ci & 1;
        int rem = tile, ti = 0;
        while (rem >= NTILE - ti) { rem -= NTILE - ti; ti++; }
        const int tj = ti + rem;
        const int vb = tj * 128 + vh * 64;

        for (int i = tid; i < 64 * N_F; i += 128) {
            int f = i >> 6, vi = i & 63;
            sh.c.v[vi][f] = x[f * C_DIM + vb + vi];
        }

        const int u = ti * 128 + tid;
        float xu[N_F];
#pragma unroll
        for (int f = 0; f < N_F; f++) xu[f] = x[f * C_DIM + u];

        __syncthreads();

        float acc[NPAIR];
#pragma unroll
        for (int k = 0; k < NPAIR; k++) acc[k] = 0.0f;

#pragma unroll 2
        for (int vi = 0; vi < 64; vi++) {
            float4 p0 = *reinterpret_cast<const float4*>(&sh.c.v[vi][0]);
            float4 p1 = *reinterpret_cast<const float4*>(&sh.c.v[vi][4]);
            float xv[N_F] = {p0.x, p0.y, p0.z, p0.w, p1.x, p1.y, p1.z, p1.w};

            float a[N_F];
#pragma unroll
            for (int f = 0; f < N_F; f++) a[f] = fabsf(xu[f] - xv[f]);

            int k = 0;
#pragma unroll
            for (int i = 0; i < N_F; i++)
#pragma unroll
                for (int j = i; j < N_F; j++) {
                    acc[k] = fmaf(a[i], a[j], acc[k]);
                    k++;
                }
        }

        // Diagonal tiles internally symmetric: weight 0.5 (self terms are 0).
        const float w = (ti == tj) ? 0.5f : 1.0f;
#pragma unroll
        for (int k = 0; k < NPAIR; k++) {
            float v = acc[k];
            for (int o = 16; o; o >>= 1) v += __shfl_down_sync(0xffffffffu, v, o);
            if (lane == 0) sh.c.red[warp][k] = v;
        }
        __syncthreads();
        if (tid < NPAIR) {
            float v = (sh.c.red[0][tid] + sh.c.red[1][tid]
                     + sh.c.red[2][tid] + sh.c.red[3][tid]) * w;
            atomicAdd(&g_stot[NPAIR + tid], v);
        }
    } else {
        // ---------- rowsum path: half-row blocks (R7-proven granularity) ----------
        const int rb = bid - NCROSSB;       // [0, 512)
        const int ut = rb >> 4;             // u-tile 0..31
        const int f = (rb >> 1) & 7;        // factor
        const int half = rb & 1;            // v-half
        const float* xf = x + f * C_DIM;
        const int vb = half * 2048;

        for (int i = tid; i < 2048; i += 128) sh.row[i] = -xf[vb + i];

        const int u = ut * 128 + tid;
        const float xu = xf[u];
        __syncthreads();

        float r0 = 0.f, r1 = 0.f, r2 = 0.f, r3 = 0.f;
        const float4* row4 = (const float4*)sh.row;
#pragma unroll 8
        for (int p = 0; p < 512; p++) {
            float4 q = row4[p];
            r0 += fabsf(xu + q.x);
            r1 += fabsf(xu + q.y);
            r2 += fabsf(xu + q.z);
            r3 += fabsf(xu + q.w);
        }
        g_rowsum2[half][f * C_DIM + u] = (r0 + r1) + (r2 + r3);

        // ---- per-u-tile ticket: 16th block of this tile reduces the rowdots ----
        __threadfence();
        if (tid == 0) sh_rank = atomicAdd(&g_tile_ctr[ut], 1);
        __syncthreads();
        if (sh_rank == 15u) {
            float r[N_F];
#pragma unroll
            for (int ff = 0; ff < N_F; ff++)
                r[ff] = __ldcg(&g_rowsum2[0][ff * C_DIM + u])
                      + __ldcg(&g_rowsum2[1][ff * C_DIM + u]);

            __syncthreads();   // smem union handoff (row -> tred)
            // Immediate shuffle-reduce per pair: one temp live at a time.
            int k = 0;
#pragma unroll
            for (int i = 0; i < N_F; i++) {
#pragma unroll
                for (int j = i; j < N_F; j++) {
                    float v = r[i] * r[j];
                    for (int o = 16; o; o >>= 1) v += __shfl_down_sync(0xffffffffu, v, o);
                    if (lane == 0) sh.tred[warp][k] = v;
                    k++;
                }
            }
#pragma unroll
            for (int ff = 0; ff < N_F; ff++) {
                float v = r[ff];
                for (int o = 16; o; o >>= 1) v += __shfl_down_sync(0xffffffffu, v, o);
                if (lane == 0) sh.tred[warp][NPAIR + ff] = v;
            }
            __syncthreads();
            if (tid < NPAIR + N_F) {
                float v = sh.tred[0][tid] + sh.tred[1][tid]
                        + sh.tred[2][tid] + sh.tred[3][tid];
                int dst = (tid < NPAIR) ? tid : (2 * NPAIR + (tid - NPAIR));
                atomicAdd(&g_stot[dst], v);
            }
            if (tid == 0) g_tile_ctr[ut] = 0;   // reset for next replay
        }
    }

    // ---------------- global ticket: last block does the 8x8 math ----------------
    __threadfence();
    if (tid == 0) sh_rank = atomicAdd(&g_ctr, 1);
    __syncthreads();
    if (sh_rank != NBLOCKS - 1) return;

    const float fC = (float)C_DIM;
    const float invC2 = 1.0f / (fC * fC);

    __syncthreads();   // smem union handoff
    if (tid < N_F) sh.e.sm[tid] = __ldcg(&g_stot[2 * NPAIR + tid]) * invC2;
    __syncthreads();

    if (tid < NPAIR) {
        int kk = tid, i = 0;
        while (kk >= N_F - i) { kk -= N_F - i; i++; }
        int j = i + kk;
        // S = 2*cross_tri/C^2 - 2*rowdot/C^3 + m_i*m_j
        float s = 2.0f * __ldcg(&g_stot[NPAIR + tid]) * invC2
                - 2.0f * __ldcg(&g_stot[tid]) * invC2 / fC
                + sh.e.sm[i] * sh.e.sm[j];
        sh.e.sdc[tid] = sqrtf(fmaxf(s, 0.0f) + EPS_F);
    }
    __syncthreads();

    if (tid == 0) {
        float cor = 0.0f;
        for (int i = 0; i < N_F; i++) {
            int di = i * N_F - (i * (i - 1)) / 2;        // k(i,i)
            for (int j = i + 1; j < N_F; j++) {
                int dj = j * N_F - (j * (j - 1)) / 2;    // k(j,j)
                int kij = di + (j - i);                   // k(i,j)
                cor += sh.e.sdc[kij] / sqrtf(sh.e.sdc[di] * sh.e.sdc[dj] + EPS_F);
            }
        }
        out[0] = cor;
    }
    __syncthreads();

    // Reset accumulators/ticket for next graph replay (all reads done above).
    if (tid < NSTOT) g_stot[tid] = 0.0f;
    if (tid == 0) g_ctr = 0;
}

extern "C" void kernel_launch(void* const* d_in, const int* in_sizes, int n_in,
                              void* d_out, int out_size) {
    const float* x = (const float*)d_in[0];
    float* out = (float*)d_out;
    main_kernel<<<NBLOCKS, 128>>>(x, out);
}

// round 14
// speedup vs baseline: 1.3102x; 1.0008x over previous
#include <cuda_runtime.h>

#define C_DIM 4096
#define N_F 8
#define NPAIR 36            // 8*9/2, i<=j
#define EPS_F 1e-8f
#define NTILE 32            // 4096 / 128
#define NROWB 512           // (u-tile, factor, v-half) rowsum blocks
#define NCROSSB (528 * 2)   // 1056: triangle tiles x 2 v-halves
#define NBLOCKS (NROWB + NCROSSB)   // 1568
#define NSTOT (2 * NPAIR + N_F)     // [0,36): rowdots  [36,72): cross  [72,80): fsum

// Device globals (statics start zero; tickets/accumulators reset for graph replay).
__device__ float g_rowsum2[2][N_F * C_DIM];  // halved rowsums
__device__ float g_stot[NSTOT];
__device__ unsigned int g_tile_ctr[NTILE];
__device__ unsigned int g_ctr = 0;

// Release-scoped ticket add: orders this thread's prior global stores/atomics
// without the L1D-flushing CCTL.IVALL that __threadfence() (gpu fence) emits.
__device__ __forceinline__ unsigned atomic_add_release(unsigned* p, unsigned v) {
    unsigned old;
    asm volatile("atom.add.release.gpu.u32 %0, [%1], %2;"
                 : "=r"(old) : "l"(p), "r"(v) : "memory");
    return old;
}
// Acquire fence — executed ONLY by winner blocks before reading peers' data.
__device__ __forceinline__ void fence_acquire_gpu() {
    asm volatile("fence.acq_rel.gpu;" ::: "memory");
}

__global__ __launch_bounds__(128, 8) void main_kernel(const float* __restrict__ x,
                                                      float* __restrict__ out) {
    __shared__ union {
        float row[2048];             // rowsum: negated v-half, 8 KB
        struct {
            float v[64][N_F];        // cross: v-half values [vi][f]
            float red[4][NPAIR];     // cross: per-warp partials
        } c;
        float tred[4][NPAIR + N_F];  // tile-reduce partials
        struct {
            float sdc[NPAIR];        // final math
            float sm[N_F];
        } e;
    } sh;
    __shared__ unsigned sh_rank;

    const int tid = threadIdx.x;
    const int bid = blockIdx.x;
    const int lane = tid & 31;
    const int warp = tid >> 5;

    if (bid < NROWB) {
        // ---------- rowsum path: half-row blocks (R7-proven granularity) ----------
        const int rb = bid;                 // [0, 512)
        const int ut = rb >> 4;             // u-tile 0..31
        const int f = (rb >> 1) & 7;        // factor
        const int half = rb & 1;            // v-half
        const float* xf = x + f * C_DIM;
        const int vb = half * 2048;

        for (int i = tid; i < 2048; i += 128) sh.row[i] = -xf[vb + i];

        const int u = ut * 128 + tid;
        const float xu = xf[u];
        __syncthreads();

        float r0 = 0.f, r1 = 0.f, r2 = 0.f, r3 = 0.f;
        const float4* row4 = (const float4*)sh.row;
#pragma unroll 8
        for (int p = 0; p < 512; p++) {
            float4 q = row4[p];
            r0 += fabsf(xu + q.x);
            r1 += fabsf(xu + q.y);
            r2 += fabsf(xu + q.z);
            r3 += fabsf(xu + q.w);
        }
        __stcg(&g_rowsum2[half][f * C_DIM + u], (r0 + r1) + (r2 + r3));

        // ---- per-u-tile ticket: 16th block of this tile reduces the rowdots ----
        if (tid == 0) sh_rank = atomic_add_release(&g_tile_ctr[ut], 1u);
        __syncthreads();
        if (sh_rank == 15u) {
            fence_acquire_gpu();   // winner only: acquire peers' stcg stores
            float r[N_F];
#pragma unroll
            for (int ff = 0; ff < N_F; ff++)
                r[ff] = __ldcg(&g_rowsum2[0][ff * C_DIM + u])
                      + __ldcg(&g_rowsum2[1][ff * C_DIM + u]);

            __syncthreads();   // smem union handoff (row -> tred)
            // Immediate shuffle-reduce per pair: one temp live at a time.
            int k = 0;
#pragma unroll
            for (int i = 0; i < N_F; i++) {
#pragma unroll
                for (int j = i; j < N_F; j++) {
                    float v = r[i] * r[j];
                    for (int o = 16; o; o >>= 1) v += __shfl_down_sync(0xffffffffu, v, o);
                    if (lane == 0) sh.tred[warp][k] = v;
                    k++;
                }
            }
#pragma unroll
            for (int ff = 0; ff < N_F; ff++) {
                float v = r[ff];
                for (int o = 16; o; o >>= 1) v += __shfl_down_sync(0xffffffffu, v, o);
                if (lane == 0) sh.tred[warp][NPAIR + ff] = v;
            }
            __syncthreads();
            if (tid < NPAIR + N_F) {
                float v = sh.tred[0][tid] + sh.tred[1][tid]
                        + sh.tred[2][tid] + sh.tred[3][tid];
                int dst = (tid < NPAIR) ? tid : (2 * NPAIR + (tid - NPAIR));
                atomicAdd(&g_stot[dst], v);
            }
            if (tid == 0) g_tile_ctr[ut] = 0;   // reset for next replay
        }
    } else {
        // ---------------- cross path (R7-proven, unchanged) ----------------
        const int ci = bid - NROWB;         // [0, 1056)
        const int tile = ci >> 1;
        const int vh = ci & 1;
        int rem = tile, ti = 0;
        while (rem >= NTILE - ti) { rem -= NTILE - ti; ti++; }
        const int tj = ti + rem;
        const int vb = tj * 128 + vh * 64;

        for (int i = tid; i < 64 * N_F; i += 128) {
            int f = i >> 6, vi = i & 63;
            sh.c.v[vi][f] = x[f * C_DIM + vb + vi];
        }

        const int u = ti * 128 + tid;
        float xu[N_F];
#pragma unroll
        for (int f = 0; f < N_F; f++) xu[f] = x[f * C_DIM + u];

        __syncthreads();

        float acc[NPAIR];
#pragma unroll
        for (int k = 0; k < NPAIR; k++) acc[k] = 0.0f;

#pragma unroll 2
        for (int vi = 0; vi < 64; vi++) {
            float4 p0 = *reinterpret_cast<const float4*>(&sh.c.v[vi][0]);
            float4 p1 = *reinterpret_cast<const float4*>(&sh.c.v[vi][4]);
            float xv[N_F] = {p0.x, p0.y, p0.z, p0.w, p1.x, p1.y, p1.z, p1.w};

            float a[N_F];
#pragma unroll
            for (int f = 0; f < N_F; f++) a[f] = fabsf(xu[f] - xv[f]);

            int k = 0;
#pragma unroll
            for (int i = 0; i < N_F; i++)
#pragma unroll
                for (int j = i; j < N_F; j++) {
                    acc[k] = fmaf(a[i], a[j], acc[k]);
                    k++;
                }
        }

        // Diagonal tiles internally symmetric: weight 0.5 (self terms are 0).
        const float w = (ti == tj) ? 0.5f : 1.0f;
#pragma unroll
        for (int k = 0; k < NPAIR; k++) {
            float v = acc[k];
            for (int o = 16; o; o >>= 1) v += __shfl_down_sync(0xffffffffu, v, o);
            if (lane == 0) sh.c.red[warp][k] = v;
        }
        __syncthreads();
        if (tid < NPAIR) {
            float v = (sh.c.red[0][tid] + sh.c.red[1][tid]
                     + sh.c.red[2][tid] + sh.c.red[3][tid]) * w;
            atomicAdd(&g_stot[NPAIR + tid], v);
        }
    }

    // ---------------- global ticket: last block does the 8x8 math ----------------
    if (tid == 0) sh_rank = atomic_add_release(&g_ctr, 1u);
    __syncthreads();
    if (sh_rank != NBLOCKS - 1) return;

    fence_acquire_gpu();   // winner only

    const float fC = (float)C_DIM;
    const float invC2 = 1.0f / (fC * fC);

    __syncthreads();   // smem union handoff
    if (tid < N_F) sh.e.sm[tid] = __ldcg(&g_stot[2 * NPAIR + tid]) * invC2;
    __syncthreads();

    if (tid < NPAIR) {
        int kk = tid, i = 0;
        while (kk >= N_F - i) { kk -= N_F - i; i++; }
        int j = i + kk;
        // S = 2*cross_tri/C^2 - 2*rowdot/C^3 + m_i*m_j
        float s = 2.0f * __ldcg(&g_stot[NPAIR + tid]) * invC2
                - 2.0f * __ldcg(&g_stot[tid]) * invC2 / fC
                + sh.e.sm[i] * sh.e.sm[j];
        sh.e.sdc[tid] = sqrtf(fmaxf(s, 0.0f) + EPS_F);
    }
    __syncthreads();

    if (tid == 0) {
        float cor = 0.0f;
        for (int i = 0; i < N_F; i++) {
            int di = i * N_F - (i * (i - 1)) / 2;        // k(i,i)
            for (int j = i + 1; j < N_F; j++) {
                int dj = j * N_F - (j * (j - 1)) / 2;    // k(j,j)
                int kij = di + (j - i);                   // k(i,j)
                cor += sh.e.sdc[kij] / sqrtf(sh.e.sdc[di] * sh.e.sdc[dj] + EPS_F);
            }
        }
        out[0] = cor;
    }
    __syncthreads();

    // Reset accumulators/ticket for next graph replay (all reads done above).
    if (tid < NSTOT) g_stot[tid] = 0.0f;
    if (tid == 0) g_ctr = 0;
}

extern "C" void kernel_launch(void* const* d_in, const int* in_sizes, int n_in,
                              void* d_out, int out_size) {
    const float* x = (const float*)d_in[0];
    float* out = (float*)d_out;
    main_kernel<<<NBLOCKS, 128>>>(x, out);
}